// round 9
// baseline (speedup 1.0000x reference)
#include <cuda_runtime.h>

#define NPTS 1024

// ---------------- packed f32x2 helpers (Blackwell) ----------------
static __device__ __forceinline__ unsigned long long pack2(float lo, float hi) {
    unsigned long long r;
    asm("mov.b64 %0, {%1,%2};" : "=l"(r) : "f"(lo), "f"(hi));
    return r;
}
static __device__ __forceinline__ float2 unpack2(unsigned long long v) {
    float2 r;
    asm("mov.b64 {%0,%1}, %2;" : "=f"(r.x), "=f"(r.y) : "l"(v));
    return r;
}
static __device__ __forceinline__ void fma2(unsigned long long& d,
                                            unsigned long long a,
                                            unsigned long long b) {
    asm("fma.rn.f32x2 %0, %1, %2, %0;" : "+l"(d) : "l"(a), "l"(b));
}

// ============================================================================
// Fused kernel: 256 blocks x 256 threads; block b owns rows 4b..4b+3.
// Phase P (pool): TWO independent 128-thread teams (named barriers), team t
//   owns rows {2t, 2t+1}. Thread = (ch-pair, k-half in lane bit 0): 2 ch x
//   32 k weights in regs (ratio: 4 fma2 per LDS.128), k-half combined via
//   __shfl_xor(1). h1 double-buffered -> 1 team barrier per 8-nbr group.
// Phase T (trunk): feat[132]->64->128->64->4 -> (a_x,a_y), f32x2 GEMV.
// ============================================================================

// ---- shared memory layout (bytes) ----
// Phase P:  s4 @0 [16384] | nbr @16384 [4][256]*4 | h1 @20480 [2tm][2buf][512]*4
//           w1s @28672 [320]*4 | b1s @29952 [64]*4 | (free)
// Phase T:  wP @0 u64[66*65]=34320 | w4 @34320 | bb1 @35344 | bb2 @35600 |
//           bb3 @36112 | b4s @36368
// Persist:  feat @36384 [4][132]*4 | cnt @38496 int[8]
#define SM_TOTAL 38528

__global__ __launch_bounds__(256, 2) void fused_kernel(
    const float* __restrict__ s, const float* __restrict__ g,
    const float* __restrict__ w1g, const float* __restrict__ b1g,
    const float* __restrict__ w2g, const float* __restrict__ b2g,
    const float* __restrict__ fc1w, const float* __restrict__ fc1b,
    const float* __restrict__ fc2w, const float* __restrict__ fc2b,
    const float* __restrict__ fc3w, const float* __restrict__ fc3b,
    const float* __restrict__ fc4w, const float* __restrict__ fc4b,
    float* __restrict__ out)
{
    __shared__ __align__(16) char smem_raw[SM_TOTAL];

    const int tid = threadIdx.x;

    // ======================= PHASE P: pool =======================
    float4* s4   = reinterpret_cast<float4*>(smem_raw);
    int (*nbr)[256] = reinterpret_cast<int(*)[256]>(smem_raw + 16384);
    float* h1    = reinterpret_cast<float*>(smem_raw + 20480);   // [2][2][512]
    float* w1s   = reinterpret_cast<float*>(smem_raw + 28672);
    float* b1s   = reinterpret_cast<float*>(smem_raw + 29952);
    float (*feat)[132] = reinterpret_cast<float(*)[132]>(smem_raw + 36384);
    int*   cnt   = reinterpret_cast<int*>(smem_raw + 38496);
    int*   cntp  = cnt + 4;

    const int team  = tid >> 7;        // team 0: warps 0-3, team 1: warps 4-7
    const int ttid  = tid & 127;
    const int khalf = ttid & 1;        // k-half in lane bit 0 (shuffle partner)
    const int chp   = ttid >> 1;       // channel pair: ch {chp, chp+64}

    // conv2 weights: 2 ch x 32 k = 16 LDG.128 -> 32 f32x2 packs (64 regs)
    unsigned long long w2p[2][16];
    float b2r[2];
#pragma unroll
    for (int c = 0; c < 2; c++) {
        int ch = chp + 64 * c;
        const float4* wr = reinterpret_cast<const float4*>(w2g + ch * 64 + khalf * 32);
        float4 wv[8];
#pragma unroll
        for (int q = 0; q < 8; q++) wv[q] = wr[q];
#pragma unroll
        for (int q = 0; q < 8; q++) {
            w2p[c][2 * q]     = pack2(wv[q].x, wv[q].y);
            w2p[c][2 * q + 1] = pack2(wv[q].z, wv[q].w);
        }
        b2r[c] = b2g[ch];
    }

    // stage s (4 batched LDG.128 each), w1, b1; reset counters
#pragma unroll
    for (int j = 0; j < 4; j++)
        s4[tid + 256 * j] = reinterpret_cast<const float4*>(s)[tid + 256 * j];
    for (int idx = tid; idx < 320; idx += 256) w1s[idx] = w1g[idx];
    if (tid < 64) b1s[tid] = b1g[tid];
    if (tid < 4)  cnt[tid] = 0;
    __syncthreads();

    const int   c1    = ttid & 63;   // conv1 channel this thread computes
    const int   slgrp = ttid >> 6;   // conv1 slot base: slots {slgrp+2t}
    const float w1r0 = w1s[c1 * 5 + 0], w1r1 = w1s[c1 * 5 + 1],
                w1r2 = w1s[c1 * 5 + 2], w1r3 = w1s[c1 * 5 + 3],
                w1r4 = w1s[c1 * 5 + 4], b1r = b1s[c1];

    const int i0 = blockIdx.x * 4;
    float4 si[4];
#pragma unroll
    for (int rr = 0; rr < 4; rr++) si[rr] = s4[i0 + rr];

    // ---- one scan pass serves all 4 rows ----
    for (int j = tid; j < NPTS; j += 256) {
        float4 sj = s4[j];
#pragma unroll
        for (int rr = 0; rr < 4; rr++) {
            float dx = si[rr].x - sj.x, dy = si[rr].y - sj.y;
            if (dx * dx + dy * dy < 0.25f) {
                int pq = atomicAdd(&cnt[rr], 1);
                nbr[rr][pq] = j;
            }
        }
    }
    __syncthreads();
    if (tid < 4) {
        int c = cnt[tid], cp = (c + 7) & ~7;
        for (int t = c; t < cp; t++) nbr[tid][t] = i0 + tid;  // self-pad (idempotent)
        cntp[tid] = cp;
    }
    __syncthreads();

    // ---- team-independent pool: 1 named barrier per 8-nbr group ----
    float* h1t = h1 + team * 1024;       // this team's two 512-float buffers
    const int barid = team + 1;          // named barrier (0 = __syncthreads)
    int buf = 0;

#pragma unroll
    for (int rr = 0; rr < 2; rr++) {
        const int    rl  = team * 2 + rr;     // row-local 0..3
        const int    i   = i0 + rl;
        const float4 sir = si[rl];
        const int    cp  = cntp[rl];
        const int*   nb  = nbr[rl];

        float p0 = 0.0f, p1 = 0.0f;   // max vs 0 covers mask zeros & relu

        for (int n = 0; n < cp; n += 8, buf ^= 1) {
            float* h1w = h1t + buf * 512;

            // conv1: thread fills h1w[c1] for slots {slgrp, +2, +4, +6}
#pragma unroll
            for (int t = 0; t < 4; t++) {
                int sl = slgrp + 2 * t;
                int j  = nb[n + sl];
                float4 sj = s4[j];
                float dx = sir.x - sj.x, dy = sir.y - sj.y;
                float dz = sir.z - sj.z, dw = sir.w - sj.w;
                float ind = (j == i) ? 1.0f : 0.0f;
                float v = b1r;
                v = fmaf(dx, w1r0, v);
                v = fmaf(dy, w1r1, v);
                v = fmaf(dz, w1r2, v);
                v = fmaf(dw, w1r3, v);
                v = fmaf(ind, w1r4, v);
                h1w[sl * 64 + c1] = fmaxf(v, 0.0f);   // conflict-free
            }
            asm volatile("bar.sync %0, 128;" :: "r"(barid) : "memory");
            // double-buffer: conv2(g) reads buf, conv1(g+1) writes buf^1 -> safe

            // conv2: 8 nbrs x 2 ch x 32 k (this k-half), 2 passes of 4 nbrs
#pragma unroll
            for (int pass = 0; pass < 2; pass++) {
                const ulonglong2* hb0 = reinterpret_cast<const ulonglong2*>(
                    h1w + (pass * 4 + 0) * 64 + khalf * 32);
                const ulonglong2* hb1 = reinterpret_cast<const ulonglong2*>(
                    h1w + (pass * 4 + 1) * 64 + khalf * 32);
                const ulonglong2* hb2 = reinterpret_cast<const ulonglong2*>(
                    h1w + (pass * 4 + 2) * 64 + khalf * 32);
                const ulonglong2* hb3 = reinterpret_cast<const ulonglong2*>(
                    h1w + (pass * 4 + 3) * 64 + khalf * 32);
                unsigned long long a00 = 0ull, a01 = 0ull, a02 = 0ull, a03 = 0ull;
                unsigned long long a10 = 0ull, a11 = 0ull, a12 = 0ull, a13 = 0ull;
#pragma unroll
                for (int q = 0; q < 8; q++) {
                    ulonglong2 h0 = hb0[q], h1v = hb1[q], h2 = hb2[q], h3 = hb3[q];
                    fma2(a00, h0.x,  w2p[0][2 * q]);
                    fma2(a01, h1v.x, w2p[0][2 * q]);
                    fma2(a02, h2.x,  w2p[0][2 * q]);
                    fma2(a03, h3.x,  w2p[0][2 * q]);
                    fma2(a10, h0.x,  w2p[1][2 * q]);
                    fma2(a11, h1v.x, w2p[1][2 * q]);
                    fma2(a12, h2.x,  w2p[1][2 * q]);
                    fma2(a13, h3.x,  w2p[1][2 * q]);
                    fma2(a00, h0.y,  w2p[0][2 * q + 1]);
                    fma2(a01, h1v.y, w2p[0][2 * q + 1]);
                    fma2(a02, h2.y,  w2p[0][2 * q + 1]);
                    fma2(a03, h3.y,  w2p[0][2 * q + 1]);
                    fma2(a10, h0.y,  w2p[1][2 * q + 1]);
                    fma2(a11, h1v.y, w2p[1][2 * q + 1]);
                    fma2(a12, h2.y,  w2p[1][2 * q + 1]);
                    fma2(a13, h3.y,  w2p[1][2 * q + 1]);
                }
                // k-half combine via adjacent-lane shuffle, then max
#pragma unroll
                for (int t = 0; t < 4; t++) {
                    unsigned long long ac0 = (t == 0) ? a00 : (t == 1) ? a01 : (t == 2) ? a02 : a03;
                    unsigned long long ac1 = (t == 0) ? a10 : (t == 1) ? a11 : (t == 2) ? a12 : a13;
                    float2 f0 = unpack2(ac0);
                    float2 f1 = unpack2(ac1);
                    float s0 = f0.x + f0.y;
                    float s1 = f1.x + f1.y;
                    s0 += __shfl_xor_sync(0xffffffffu, s0, 1);
                    s1 += __shfl_xor_sync(0xffffffffu, s1, 1);
                    p0 = fmaxf(p0, s0 + b2r[0]);
                    p1 = fmaxf(p1, s1 + b2r[1]);
                }
            }
        }

        if (khalf == 0) {
            feat[rl][chp]      = p0;
            feat[rl][chp + 64] = p1;
        }
    }
    __syncthreads();   // both teams done; P-phase smem dead -> overlay T

    // ======================= PHASE T: trunk =======================
    unsigned long long* wP = reinterpret_cast<unsigned long long*>(smem_raw);
    float* w4  = reinterpret_cast<float*>(smem_raw + 34320);
    float* bb1 = reinterpret_cast<float*>(smem_raw + 35344);
    float* bb2 = reinterpret_cast<float*>(smem_raw + 35600);
    float* bb3 = reinterpret_cast<float*>(smem_raw + 36112);
    float* b4s = reinterpret_cast<float*>(smem_raw + 36368);
    float (*act)[132] = feat;   // same storage

    const int lane   = tid & 31;
    const int w      = tid >> 5;
    const bool active = (w < 4);
    const int r      = i0 + (active ? w : 0);

    float4 sv = make_float4(0.f, 0.f, 0.f, 0.f);
    float2 gv = make_float2(0.f, 0.f);
    if (active) {
        sv = reinterpret_cast<const float4*>(s)[r];
        gv = reinterpret_cast<const float2*>(g)[r];
        if (lane == 0) {
            act[w][128] = sv.x - gv.x;
            act[w][129] = sv.y - gv.y;
            act[w][130] = sv.z;
            act[w][131] = sv.w;
        }
    }

    // fc1 staging loads: 2112 float4, register-buffered
    const float4* f1w4 = reinterpret_cast<const float4*>(fc1w);
    float4 v1[8];
#pragma unroll
    for (int rr = 0; rr < 8; rr++) v1[rr] = f1w4[tid + 256 * rr];
    float4 v1x;
    if (tid < 64) v1x = f1w4[2048 + tid];

    // biases + fc4
    if (tid < 64)  bb1[tid] = fc1b[tid];
    if (tid < 128) bb2[tid] = fc2b[tid];
    if (tid >= 128 && tid < 192) bb3[tid - 128] = fc3b[tid - 128];
    if (tid < 4)   b4s[tid] = fc4b[tid];
    if (tid < 64) {                       // fc4: 64 float4s
        float4 v = reinterpret_cast<const float4*>(fc4w)[tid];
        int o = tid >> 4;
        int k = (tid << 2) & 63;
        w4[(k + 0) * 4 + o] = v.x; w4[(k + 1) * 4 + o] = v.y;
        w4[(k + 2) * 4 + o] = v.z; w4[(k + 3) * 4 + o] = v.w;
    }

    // STS fc1 as k-pair u64: wP[k2*65 + o]
#pragma unroll
    for (int rr = 0; rr < 8; rr++) {
        int e = (tid + 256 * rr) << 2;
        int o = e / 132;                  // 132 % 4 == 0: no row straddle
        int k = e - o * 132;
        int k2 = k >> 1;
        wP[(k2 + 0) * 65 + o] = pack2(v1[rr].x, v1[rr].y);
        wP[(k2 + 1) * 65 + o] = pack2(v1[rr].z, v1[rr].w);
    }
    if (tid < 64) {
        int e = (2048 + tid) << 2;
        int o = e / 132;
        int k = e - o * 132;
        int k2 = k >> 1;
        wP[(k2 + 0) * 65 + o] = pack2(v1x.x, v1x.y);
        wP[(k2 + 1) * 65 + o] = pack2(v1x.z, v1x.w);
    }
    __syncthreads();

    // prefetch fc2 before L1 compute
    const float4* f2w4 = reinterpret_cast<const float4*>(fc2w);
    float4 v2[8];
#pragma unroll
    for (int rr = 0; rr < 8; rr++) v2[rr] = f2w4[tid + 256 * rr];

    // L1: 132 -> 64
    {
        float a0 = 0.f, a1 = 0.f;
        if (active) {
            const unsigned long long* actp =
                reinterpret_cast<const unsigned long long*>(act[w]);
            unsigned long long a0p = 0ull, a1p = 0ull;
#pragma unroll 6
            for (int k2 = 0; k2 < 66; k2++) {
                unsigned long long ap = actp[k2];
                fma2(a0p, ap, wP[k2 * 65 + lane]);
                fma2(a1p, ap, wP[k2 * 65 + lane + 32]);
            }
            float2 f0 = unpack2(a0p), f1 = unpack2(a1p);
            a0 = fmaxf(f0.x + f0.y + bb1[lane], 0.0f);
            a1 = fmaxf(f1.x + f1.y + bb1[lane + 32], 0.0f);
        }
        __syncthreads();
        if (active) { act[w][lane] = a0; act[w][lane + 32] = a1; }
    }

    // STS fc2: [128][64] -> wP[k2*129 + o]
#pragma unroll
    for (int rr = 0; rr < 8; rr++) {
        int e = (tid + 256 * rr) << 2;
        int o = e >> 6;
        int k = e & 63;
        int k2 = k >> 1;
        wP[(k2 + 0) * 129 + o] = pack2(v2[rr].x, v2[rr].y);
        wP[(k2 + 1) * 129 + o] = pack2(v2[rr].z, v2[rr].w);
    }
    __syncthreads();

    // prefetch fc3 before L2 compute
    const float4* f3w4 = reinterpret_cast<const float4*>(fc3w);
    float4 v3[8];
#pragma unroll
    for (int rr = 0; rr < 8; rr++) v3[rr] = f3w4[tid + 256 * rr];

    // L2: 64 -> 128
    {
        float o0 = 0.f, o1 = 0.f, o2 = 0.f, o3 = 0.f;
        if (active) {
            const unsigned long long* actp =
                reinterpret_cast<const unsigned long long*>(act[w]);
            unsigned long long ac[4] = {0ull, 0ull, 0ull, 0ull};
#pragma unroll 4
            for (int k2 = 0; k2 < 32; k2++) {
                unsigned long long ap = actp[k2];
                fma2(ac[0], ap, wP[k2 * 129 + lane]);
                fma2(ac[1], ap, wP[k2 * 129 + lane + 32]);
                fma2(ac[2], ap, wP[k2 * 129 + lane + 64]);
                fma2(ac[3], ap, wP[k2 * 129 + lane + 96]);
            }
            { float2 f = unpack2(ac[0]); o0 = fmaxf(f.x + f.y + bb2[lane],      0.0f); }
            { float2 f = unpack2(ac[1]); o1 = fmaxf(f.x + f.y + bb2[lane + 32], 0.0f); }
            { float2 f = unpack2(ac[2]); o2 = fmaxf(f.x + f.y + bb2[lane + 64], 0.0f); }
            { float2 f = unpack2(ac[3]); o3 = fmaxf(f.x + f.y + bb2[lane + 96], 0.0f); }
        }
        __syncthreads();
        if (active) {
            act[w][lane] = o0; act[w][lane + 32] = o1;
            act[w][lane + 64] = o2; act[w][lane + 96] = o3;
        }
    }

    // STS fc3: [64][128] -> wP[k2*65 + o]
#pragma unroll
    for (int rr = 0; rr < 8; rr++) {
        int e = (tid + 256 * rr) << 2;
        int o = e >> 7;
        int k = e & 127;
        int k2 = k >> 1;
        wP[(k2 + 0) * 65 + o] = pack2(v3[rr].x, v3[rr].y);
        wP[(k2 + 1) * 65 + o] = pack2(v3[rr].z, v3[rr].w);
    }
    __syncthreads();

    if (active) {
        // L3: 128 -> 64 (warp-private from here on)
        const unsigned long long* actp =
            reinterpret_cast<const unsigned long long*>(act[w]);
        unsigned long long a0p = 0ull, a1p = 0ull;
#pragma unroll 8
        for (int k2 = 0; k2 < 64; k2++) {
            unsigned long long ap = actp[k2];
            fma2(a0p, ap, wP[k2 * 65 + lane]);
            fma2(a1p, ap, wP[k2 * 65 + lane + 32]);
        }
        float2 f0 = unpack2(a0p), f1 = unpack2(a1p);
        float a0 = fmaxf(f0.x + f0.y + bb3[lane], 0.0f);
        float a1 = fmaxf(f1.x + f1.y + bb3[lane + 32], 0.0f);
        __syncwarp();
        act[w][lane] = a0; act[w][lane + 32] = a1;
        __syncwarp();

        // L4: 64 -> 4, sigmoid, gains
        int ol = lane & 3;
        float acc = b4s[ol];
#pragma unroll 4
        for (int k = 0; k < 64; k++)
            acc = fmaf(act[w][k], w4[k * 4 + ol], acc);
        float kv = 2.0f / (1.0f + expf(-acc)) - 1.0f;

        float k1 = __shfl_sync(0xffffffffu, kv, 0);
        float k2 = __shfl_sync(0xffffffffu, kv, 1);
        float k3 = __shfl_sync(0xffffffffu, kv, 2);
        float k4 = __shfl_sync(0xffffffffu, kv, 3);

        if (lane == 0) {
            float sg0 = sv.x - gv.x;
            float sg1 = sv.y - gv.y;
            out[r * 2 + 0] = -(k1 * sg0 + k2 * sv.z);
            out[r * 2 + 1] = -(k3 * sg1 + k4 * sv.w);
        }
    }
}

// ============================================================================
extern "C" void kernel_launch(void* const* d_in, const int* in_sizes, int n_in,
                              void* d_out, int out_size)
{
    const float* s    = (const float*)d_in[0];
    const float* g    = (const float*)d_in[1];
    const float* c1w  = (const float*)d_in[2];
    const float* c1b  = (const float*)d_in[3];
    const float* c2w  = (const float*)d_in[4];
    const float* c2b  = (const float*)d_in[5];
    const float* f1w  = (const float*)d_in[6];
    const float* f1b  = (const float*)d_in[7];
    const float* f2w  = (const float*)d_in[8];
    const float* f2b  = (const float*)d_in[9];
    const float* f3w  = (const float*)d_in[10];
    const float* f3b  = (const float*)d_in[11];
    const float* f4w  = (const float*)d_in[12];
    const float* f4b  = (const float*)d_in[13];
    float* out = (float*)d_out;

    fused_kernel<<<NPTS / 4, 256>>>(s, g, c1w, c1b, c2w, c2b,
                                    f1w, f1b, f2w, f2b, f3w, f3b,
                                    f4w, f4b, out);
}

// round 10
// speedup vs baseline: 1.1752x; 1.1752x over previous
#include <cuda_runtime.h>

#define NPTS 1024

// ---------------- packed f32x2 helpers (Blackwell) ----------------
static __device__ __forceinline__ unsigned long long pack2(float lo, float hi) {
    unsigned long long r;
    asm("mov.b64 %0, {%1,%2};" : "=l"(r) : "f"(lo), "f"(hi));
    return r;
}
static __device__ __forceinline__ float2 unpack2(unsigned long long v) {
    float2 r;
    asm("mov.b64 {%0,%1}, %2;" : "=f"(r.x), "=f"(r.y) : "l"(v));
    return r;
}
static __device__ __forceinline__ void fma2(unsigned long long& d,
                                            unsigned long long a,
                                            unsigned long long b) {
    asm("fma.rn.f32x2 %0, %1, %2, %0;" : "+l"(d) : "l"(a), "l"(b));
}

// ============================================================================
// Fused kernel: 256 blocks x 256 threads; block b owns rows 4b..4b+3.
// Phase P (pool): chunked, nearly barrier-free.
//   conv1 fills h1 for up to 64 neighbors (1 barrier), then conv2 sweeps the
//   whole chunk with NO barriers. Thread = (khalf in lane bit 0, ch-pair,
//   nnset). k-half combined via shfl_xor(1). h1 padded to 36 floats per
//   khalf (khalf stride 144B) so the two per-warp LDS.128 addresses hit
//   disjoint bank groups (conflict-free broadcast).
// Phase T (trunk): feat[132]->64->128->64->4 -> (a_x,a_y), f32x2 GEMV.
// ============================================================================

// ---- shared memory layout (bytes) ----
// Phase P: s4 @0 [16384] | nbr @16384 [4][256]*4 | h1 @20480 [64][2][36]*4=18432
//          w1s @38912 [320]*4 | b1s @40192 [64]*4 | part @40448 [4*128]*4
// Phase T: wP @0 u64[66*65]=34320 | w4 @34320 | bb1 @35344 | bb2 @35600 |
//          bb3 @36112 | b4s @36368
// Persist: cnt @42496 int[8] | feat @42528 [4][132]*4 -> end 44640
#define SM_TOTAL 44672

__global__ __launch_bounds__(256, 2) void fused_kernel(
    const float* __restrict__ s, const float* __restrict__ g,
    const float* __restrict__ w1g, const float* __restrict__ b1g,
    const float* __restrict__ w2g, const float* __restrict__ b2g,
    const float* __restrict__ fc1w, const float* __restrict__ fc1b,
    const float* __restrict__ fc2w, const float* __restrict__ fc2b,
    const float* __restrict__ fc3w, const float* __restrict__ fc3b,
    const float* __restrict__ fc4w, const float* __restrict__ fc4b,
    float* __restrict__ out)
{
    __shared__ __align__(16) char smem_raw[SM_TOTAL];

    const int tid = threadIdx.x;

    // ======================= PHASE P: pool =======================
    float4* s4   = reinterpret_cast<float4*>(smem_raw);
    int (*nbr)[256] = reinterpret_cast<int(*)[256]>(smem_raw + 16384);
    float* h1    = reinterpret_cast<float*>(smem_raw + 20480);   // [64][2][36]
    float* w1s   = reinterpret_cast<float*>(smem_raw + 38912);
    float* b1s   = reinterpret_cast<float*>(smem_raw + 40192);
    float* part  = reinterpret_cast<float*>(smem_raw + 40448);   // [4][128]
    int*   cnt   = reinterpret_cast<int*>(smem_raw + 42496);
    int*   cntp  = cnt + 4;
    float (*feat)[132] = reinterpret_cast<float(*)[132]>(smem_raw + 42528);

    const int khalf = tid & 1;          // k-half, lane bit 0 (shuffle partner)
    const int chp   = (tid >> 1) & 63;  // channel pair: ch {chp, chp+64}
    const int nnset = tid >> 7;         // neighbor subset (4 of each 8)

    // conv2 weights: 2 ch x 32 k (this k-half): 16 LDG.128 -> 32 f32x2 packs
    unsigned long long w2p[2][16];
    float b2r[2];
#pragma unroll
    for (int c = 0; c < 2; c++) {
        int ch = chp + 64 * c;
        const float4* wr = reinterpret_cast<const float4*>(w2g + ch * 64 + khalf * 32);
        float4 wv[8];
#pragma unroll
        for (int q = 0; q < 8; q++) wv[q] = wr[q];
#pragma unroll
        for (int q = 0; q < 8; q++) {
            w2p[c][2 * q]     = pack2(wv[q].x, wv[q].y);
            w2p[c][2 * q + 1] = pack2(wv[q].z, wv[q].w);
        }
        b2r[c] = b2g[ch];
    }

    // stage s (4 batched LDG.128 each), w1, b1; reset counters
#pragma unroll
    for (int j = 0; j < 4; j++)
        s4[tid + 256 * j] = reinterpret_cast<const float4*>(s)[tid + 256 * j];
    for (int idx = tid; idx < 320; idx += 256) w1s[idx] = w1g[idx];
    if (tid < 64) b1s[tid] = b1g[tid];
    if (tid < 4)  cnt[tid] = 0;
    __syncthreads();

    const int   c1  = tid & 63;   // conv1 channel this thread computes
    const int   slb = tid >> 6;   // conv1 slot base: slots {slb + 4t}
    const float w1r0 = w1s[c1 * 5 + 0], w1r1 = w1s[c1 * 5 + 1],
                w1r2 = w1s[c1 * 5 + 2], w1r3 = w1s[c1 * 5 + 3],
                w1r4 = w1s[c1 * 5 + 4], b1r = b1s[c1];
    const int   h1wr = (c1 >> 5) * 36 + (c1 & 31);   // conv1 write offset in slot

    const int i0 = blockIdx.x * 4;
    float4 si[4];
#pragma unroll
    for (int rr = 0; rr < 4; rr++) si[rr] = s4[i0 + rr];

    // ---- one scan pass serves all 4 rows ----
    for (int j = tid; j < NPTS; j += 256) {
        float4 sj = s4[j];
#pragma unroll
        for (int rr = 0; rr < 4; rr++) {
            float dx = si[rr].x - sj.x, dy = si[rr].y - sj.y;
            if (dx * dx + dy * dy < 0.25f) {
                int pq = atomicAdd(&cnt[rr], 1);
                nbr[rr][pq] = j;
            }
        }
    }
    __syncthreads();
    if (tid < 4) {
        int c = cnt[tid], cp = (c + 7) & ~7;
        for (int t = c; t < cp; t++) nbr[tid][t] = i0 + tid;  // self-pad (idempotent)
        cntp[tid] = cp;
    }
    __syncthreads();

    // ---- pool: 64-neighbor chunks; conv2 sweeps are barrier-free ----
    float pr0[4], pr1[4];
#pragma unroll
    for (int rr = 0; rr < 4; rr++) { pr0[rr] = 0.0f; pr1[rr] = 0.0f; }

#pragma unroll 1
    for (int rr = 0; rr < 4; rr++) {
        const float4 sir = si[rr];
        const int    i   = i0 + rr;
        const int    cp  = cntp[rr];
        const int*   nb  = nbr[rr];
        float p0 = 0.0f, p1 = 0.0f;   // max vs 0 covers mask zeros & relu

        for (int chunk = 0; chunk < cp; chunk += 64) {
            const int clen = min(64, cp - chunk);   // multiple of 8

            // conv1: fill h1 for clen slots (16 slots/thread, warp-uniform guard)
#pragma unroll 4
            for (int t = 0; t < 16; t++) {
                int sl = slb + 4 * t;
                if (sl < clen) {
                    int j = nb[chunk + sl];
                    float4 sj = s4[j];
                    float dx = sir.x - sj.x, dy = sir.y - sj.y;
                    float dz = sir.z - sj.z, dw = sir.w - sj.w;
                    float ind = (j == i) ? 1.0f : 0.0f;
                    float v = b1r;
                    v = fmaf(dx, w1r0, v);
                    v = fmaf(dy, w1r1, v);
                    v = fmaf(dz, w1r2, v);
                    v = fmaf(dw, w1r3, v);
                    v = fmaf(ind, w1r4, v);
                    h1[sl * 72 + h1wr] = fmaxf(v, 0.0f);   // conflict-free
                }
            }
            __syncthreads();   // h1 chunk ready

            // conv2 sweep: NO barriers inside the chunk
            for (int n = 0; n < clen; n += 8) {
                const float* hb = h1 + (n + nnset * 4) * 72 + khalf * 36;
                unsigned long long a00 = 0ull, a01 = 0ull;
                unsigned long long a10 = 0ull, a11 = 0ull;
                unsigned long long a20 = 0ull, a21 = 0ull;
                unsigned long long a30 = 0ull, a31 = 0ull;
#pragma unroll
                for (int q = 0; q < 8; q++) {
                    // per warp: two 16B addrs (khalf 0/1) on disjoint banks
                    ulonglong2 h0 = *reinterpret_cast<const ulonglong2*>(hb + 0 * 72 + q * 4);
                    ulonglong2 hv1 = *reinterpret_cast<const ulonglong2*>(hb + 1 * 72 + q * 4);
                    ulonglong2 h2 = *reinterpret_cast<const ulonglong2*>(hb + 2 * 72 + q * 4);
                    ulonglong2 h3 = *reinterpret_cast<const ulonglong2*>(hb + 3 * 72 + q * 4);
                    unsigned long long wa = w2p[0][2 * q], wb = w2p[0][2 * q + 1];
                    unsigned long long wc = w2p[1][2 * q], wd = w2p[1][2 * q + 1];
                    fma2(a00, h0.x,  wa); fma2(a00, h0.y,  wb);
                    fma2(a10, hv1.x, wa); fma2(a10, hv1.y, wb);
                    fma2(a20, h2.x,  wa); fma2(a20, h2.y,  wb);
                    fma2(a30, h3.x,  wa); fma2(a30, h3.y,  wb);
                    fma2(a01, h0.x,  wc); fma2(a01, h0.y,  wd);
                    fma2(a11, hv1.x, wc); fma2(a11, hv1.y, wd);
                    fma2(a21, h2.x,  wc); fma2(a21, h2.y,  wd);
                    fma2(a31, h3.x,  wc); fma2(a31, h3.y,  wd);
                }
                // k-half combine via adjacent-lane shuffle (no smem, no bar)
#pragma unroll
                for (int t = 0; t < 4; t++) {
                    unsigned long long ac0 = (t == 0) ? a00 : (t == 1) ? a10 : (t == 2) ? a20 : a30;
                    unsigned long long ac1 = (t == 0) ? a01 : (t == 1) ? a11 : (t == 2) ? a21 : a31;
                    float2 f0 = unpack2(ac0);
                    float2 f1 = unpack2(ac1);
                    float s0 = f0.x + f0.y;
                    float s1 = f1.x + f1.y;
                    s0 += __shfl_xor_sync(0xffffffffu, s0, 1);
                    s1 += __shfl_xor_sync(0xffffffffu, s1, 1);
                    p0 = fmaxf(p0, s0 + b2r[0]);
                    p1 = fmaxf(p1, s1 + b2r[1]);
                }
            }
            __syncthreads();   // all reads of h1 done before next chunk/row
        }
        pr0[rr] = p0; pr1[rr] = p1;
    }

    // ---- combine the two nnsets (one reduce for all 4 rows) ----
    if (nnset == 1 && khalf == 0) {
#pragma unroll
        for (int rr = 0; rr < 4; rr++) {
            part[rr * 128 + chp]      = pr0[rr];
            part[rr * 128 + chp + 64] = pr1[rr];
        }
    }
    __syncthreads();
    if (nnset == 0 && khalf == 0) {
#pragma unroll
        for (int rr = 0; rr < 4; rr++) {
            feat[rr][chp]      = fmaxf(pr0[rr], part[rr * 128 + chp]);
            feat[rr][chp + 64] = fmaxf(pr1[rr], part[rr * 128 + chp + 64]);
        }
    }
    __syncthreads();   // P-phase smem dead; safe to overlay T-phase data

    // ======================= PHASE T: trunk =======================
    unsigned long long* wP = reinterpret_cast<unsigned long long*>(smem_raw);
    float* w4  = reinterpret_cast<float*>(smem_raw + 34320);
    float* bb1 = reinterpret_cast<float*>(smem_raw + 35344);
    float* bb2 = reinterpret_cast<float*>(smem_raw + 35600);
    float* bb3 = reinterpret_cast<float*>(smem_raw + 36112);
    float* b4s = reinterpret_cast<float*>(smem_raw + 36368);
    float (*act)[132] = feat;   // same storage (outside trunk weight area)

    const int lane   = tid & 31;
    const int w      = tid >> 5;
    const bool active = (w < 4);
    const int r      = i0 + (active ? w : 0);

    float4 sv = make_float4(0.f, 0.f, 0.f, 0.f);
    float2 gv = make_float2(0.f, 0.f);
    if (active) {
        sv = reinterpret_cast<const float4*>(s)[r];
        gv = reinterpret_cast<const float2*>(g)[r];
        if (lane == 0) {
            act[w][128] = sv.x - gv.x;
            act[w][129] = sv.y - gv.y;
            act[w][130] = sv.z;
            act[w][131] = sv.w;
        }
    }

    // fc1 staging loads: 2112 float4, register-buffered
    const float4* f1w4 = reinterpret_cast<const float4*>(fc1w);
    float4 v1[8];
#pragma unroll
    for (int rr = 0; rr < 8; rr++) v1[rr] = f1w4[tid + 256 * rr];
    float4 v1x;
    if (tid < 64) v1x = f1w4[2048 + tid];

    // biases + fc4
    if (tid < 64)  bb1[tid] = fc1b[tid];
    if (tid < 128) bb2[tid] = fc2b[tid];
    if (tid >= 128 && tid < 192) bb3[tid - 128] = fc3b[tid - 128];
    if (tid < 4)   b4s[tid] = fc4b[tid];
    if (tid < 64) {                       // fc4: 64 float4s
        float4 v = reinterpret_cast<const float4*>(fc4w)[tid];
        int o = tid >> 4;
        int k = (tid << 2) & 63;
        w4[(k + 0) * 4 + o] = v.x; w4[(k + 1) * 4 + o] = v.y;
        w4[(k + 2) * 4 + o] = v.z; w4[(k + 3) * 4 + o] = v.w;
    }

    // STS fc1 as k-pair u64: wP[k2*65 + o]
#pragma unroll
    for (int rr = 0; rr < 8; rr++) {
        int e = (tid + 256 * rr) << 2;
        int o = e / 132;                  // 132 % 4 == 0: no row straddle
        int k = e - o * 132;
        int k2 = k >> 1;
        wP[(k2 + 0) * 65 + o] = pack2(v1[rr].x, v1[rr].y);
        wP[(k2 + 1) * 65 + o] = pack2(v1[rr].z, v1[rr].w);
    }
    if (tid < 64) {
        int e = (2048 + tid) << 2;
        int o = e / 132;
        int k = e - o * 132;
        int k2 = k >> 1;
        wP[(k2 + 0) * 65 + o] = pack2(v1x.x, v1x.y);
        wP[(k2 + 1) * 65 + o] = pack2(v1x.z, v1x.w);
    }
    __syncthreads();

    // prefetch fc2 before L1 compute
    const float4* f2w4 = reinterpret_cast<const float4*>(fc2w);
    float4 v2[8];
#pragma unroll
    for (int rr = 0; rr < 8; rr++) v2[rr] = f2w4[tid + 256 * rr];

    // L1: 132 -> 64
    {
        float a0 = 0.f, a1 = 0.f;
        if (active) {
            const unsigned long long* actp =
                reinterpret_cast<const unsigned long long*>(act[w]);
            unsigned long long a0p = 0ull, a1p = 0ull;
#pragma unroll 6
            for (int k2 = 0; k2 < 66; k2++) {
                unsigned long long ap = actp[k2];
                fma2(a0p, ap, wP[k2 * 65 + lane]);
                fma2(a1p, ap, wP[k2 * 65 + lane + 32]);
            }
            float2 f0 = unpack2(a0p), f1 = unpack2(a1p);
            a0 = fmaxf(f0.x + f0.y + bb1[lane], 0.0f);
            a1 = fmaxf(f1.x + f1.y + bb1[lane + 32], 0.0f);
        }
        __syncthreads();
        if (active) { act[w][lane] = a0; act[w][lane + 32] = a1; }
    }

    // STS fc2: [128][64] -> wP[k2*129 + o]
#pragma unroll
    for (int rr = 0; rr < 8; rr++) {
        int e = (tid + 256 * rr) << 2;
        int o = e >> 6;
        int k = e & 63;
        int k2 = k >> 1;
        wP[(k2 + 0) * 129 + o] = pack2(v2[rr].x, v2[rr].y);
        wP[(k2 + 1) * 129 + o] = pack2(v2[rr].z, v2[rr].w);
    }
    __syncthreads();

    // prefetch fc3 before L2 compute
    const float4* f3w4 = reinterpret_cast<const float4*>(fc3w);
    float4 v3[8];
#pragma unroll
    for (int rr = 0; rr < 8; rr++) v3[rr] = f3w4[tid + 256 * rr];

    // L2: 64 -> 128
    {
        float o0 = 0.f, o1 = 0.f, o2 = 0.f, o3 = 0.f;
        if (active) {
            const unsigned long long* actp =
                reinterpret_cast<const unsigned long long*>(act[w]);
            unsigned long long ac[4] = {0ull, 0ull, 0ull, 0ull};
#pragma unroll 4
            for (int k2 = 0; k2 < 32; k2++) {
                unsigned long long ap = actp[k2];
                fma2(ac[0], ap, wP[k2 * 129 + lane]);
                fma2(ac[1], ap, wP[k2 * 129 + lane + 32]);
                fma2(ac[2], ap, wP[k2 * 129 + lane + 64]);
                fma2(ac[3], ap, wP[k2 * 129 + lane + 96]);
            }
            { float2 f = unpack2(ac[0]); o0 = fmaxf(f.x + f.y + bb2[lane],      0.0f); }
            { float2 f = unpack2(ac[1]); o1 = fmaxf(f.x + f.y + bb2[lane + 32], 0.0f); }
            { float2 f = unpack2(ac[2]); o2 = fmaxf(f.x + f.y + bb2[lane + 64], 0.0f); }
            { float2 f = unpack2(ac[3]); o3 = fmaxf(f.x + f.y + bb2[lane + 96], 0.0f); }
        }
        __syncthreads();
        if (active) {
            act[w][lane] = o0; act[w][lane + 32] = o1;
            act[w][lane + 64] = o2; act[w][lane + 96] = o3;
        }
    }

    // STS fc3: [64][128] -> wP[k2*65 + o]
#pragma unroll
    for (int rr = 0; rr < 8; rr++) {
        int e = (tid + 256 * rr) << 2;
        int o = e >> 7;
        int k = e & 127;
        int k2 = k >> 1;
        wP[(k2 + 0) * 65 + o] = pack2(v3[rr].x, v3[rr].y);
        wP[(k2 + 1) * 65 + o] = pack2(v3[rr].z, v3[rr].w);
    }
    __syncthreads();

    if (active) {
        // L3: 128 -> 64 (warp-private from here on)
        const unsigned long long* actp =
            reinterpret_cast<const unsigned long long*>(act[w]);
        unsigned long long a0p = 0ull, a1p = 0ull;
#pragma unroll 8
        for (int k2 = 0; k2 < 64; k2++) {
            unsigned long long ap = actp[k2];
            fma2(a0p, ap, wP[k2 * 65 + lane]);
            fma2(a1p, ap, wP[k2 * 65 + lane + 32]);
        }
        float2 f0 = unpack2(a0p), f1 = unpack2(a1p);
        float a0 = fmaxf(f0.x + f0.y + bb3[lane], 0.0f);
        float a1 = fmaxf(f1.x + f1.y + bb3[lane + 32], 0.0f);
        __syncwarp();
        act[w][lane] = a0; act[w][lane + 32] = a1;
        __syncwarp();

        // L4: 64 -> 4, sigmoid, gains
        int ol = lane & 3;
        float acc = b4s[ol];
#pragma unroll 4
        for (int k = 0; k < 64; k++)
            acc = fmaf(act[w][k], w4[k * 4 + ol], acc);
        float kv = 2.0f / (1.0f + expf(-acc)) - 1.0f;

        float k1 = __shfl_sync(0xffffffffu, kv, 0);
        float k2 = __shfl_sync(0xffffffffu, kv, 1);
        float k3 = __shfl_sync(0xffffffffu, kv, 2);
        float k4 = __shfl_sync(0xffffffffu, kv, 3);

        if (lane == 0) {
            float sg0 = sv.x - gv.x;
            float sg1 = sv.y - gv.y;
            out[r * 2 + 0] = -(k1 * sg0 + k2 * sv.z);
            out[r * 2 + 1] = -(k3 * sg1 + k4 * sv.w);
        }
    }
}

// ============================================================================
extern "C" void kernel_launch(void* const* d_in, const int* in_sizes, int n_in,
                              void* d_out, int out_size)
{
    const float* s    = (const float*)d_in[0];
    const float* g    = (const float*)d_in[1];
    const float* c1w  = (const float*)d_in[2];
    const float* c1b  = (const float*)d_in[3];
    const float* c2w  = (const float*)d_in[4];
    const float* c2b  = (const float*)d_in[5];
    const float* f1w  = (const float*)d_in[6];
    const float* f1b  = (const float*)d_in[7];
    const float* f2w  = (const float*)d_in[8];
    const float* f2b  = (const float*)d_in[9];
    const float* f3w  = (const float*)d_in[10];
    const float* f3b  = (const float*)d_in[11];
    const float* f4w  = (const float*)d_in[12];
    const float* f4b  = (const float*)d_in[13];
    float* out = (float*)d_out;

    fused_kernel<<<NPTS / 4, 256>>>(s, g, c1w, c1b, c2w, c2b,
                                    f1w, f1b, f2w, f2b, f3w, f3b,
                                    f4w, f4b, out);
}